// round 12
// baseline (speedup 1.0000x reference)
#include <cuda_runtime.h>
#include <cuda_fp16.h>
#include <cstdint>

// Problem constants
#define Dc     256
#define Kc     1024
#define HWc    1024
#define NTOK   65536
#define NELEM  16777216

#define NBLK   512          // token blocks of 128
#define M_TILE 128
#define NCHUNK 8
#define NSTG   8
#define NTHR   544          // 16 compute warps + 1 producer warp
#define THRESH 0.25f
#define FTOK   16           // tokens per fixup work-item group

// PRE-SWIZZLED fp16-hi codebook image only (A now converted in-kernel):
__device__ __align__(128) unsigned char gB[8 * 8 * 8192];           // 512 KB
__device__ float g_cnorm[Kc];
__device__ int   g_idx[NTOK];
__device__ int   g_nfix;
__device__ int   g_fixlist[NTOK];
__device__ unsigned long long g_fixbest[NTOK];

// dynamic smem layout (argmin kernel)
#define SM_A     0          // 64KB: 8 stage tiles (fp16, swizzled)
#define SM_B     65536      // 2 chunk buffers x 64KB = 128KB (buf1 doubles as f32 prep staging)
#define SM_CN    196608     // 4KB
#define SM_BEST  200704     // 1KB
#define SM_BEST2 201728     // 512B
#define SM_MB    202240     // full[2] @ +0, empty[2] @ +16, prep @ +32
#define SM_TOTAL 202368

// dynamic smem layout (fixup kernel)
#define FX_XS    0          // [16][256] f32 = 16KB
#define FX_CBT   16384      // [32][256] f32 = 32KB
#define FX_SB    49152      // [16] u64
#define FX_TOTAL 49280

__device__ __forceinline__ uint32_t smem_u32(const void* p) {
    uint32_t a;
    asm("{ .reg .u64 t; cvta.to.shared.u64 t, %1; cvt.u32.u64 %0, t; }" : "=r"(a) : "l"(p));
    return a;
}
__device__ __forceinline__ void bulk_copy(uint32_t dst, const void* src,
                                          uint32_t bytes, uint32_t mbar) {
    asm volatile(
        "cp.async.bulk.shared::cluster.global.mbarrier::complete_tx::bytes "
        "[%0], [%1], %2, [%3];"
        :: "r"(dst), "l"(src), "r"(bytes), "r"(mbar) : "memory");
}
#define MBAR_INIT(a, c)   asm volatile("mbarrier.init.shared.b64 [%0], %1;" :: "r"(a), "r"(c) : "memory")
#define MBAR_EXPECT(a, b) asm volatile("mbarrier.arrive.expect_tx.shared.b64 _, [%0], %1;" :: "r"(a), "r"(b) : "memory")
#define MBAR_ARRIVE(a)    asm volatile("mbarrier.arrive.shared.b64 _, [%0];" :: "r"(a) : "memory")

__device__ __forceinline__ void mbar_wait(uint32_t mbar, uint32_t parity) {
    asm volatile(
        "{\n\t.reg .pred P1;\n\t"
        "WAIT_LOOP_%=:\n\t"
        "mbarrier.try_wait.parity.acquire.cta.shared::cta.b64 P1, [%0], %1, 0x989680;\n\t"
        "@P1 bra.uni WAIT_DONE_%=;\n\t"
        "bra.uni WAIT_LOOP_%=;\n\t"
        "WAIT_DONE_%=:\n\t}"
        :: "r"(mbar), "r"(parity) : "memory");
}

__device__ __forceinline__ void ldsm4(uint32_t& r0, uint32_t& r1, uint32_t& r2, uint32_t& r3,
                                      uint32_t addr) {
    asm volatile("ldmatrix.sync.aligned.m8n8.x4.shared.b16 {%0,%1,%2,%3}, [%4];"
                 : "=r"(r0), "=r"(r1), "=r"(r2), "=r"(r3) : "r"(addr));
}
__device__ __forceinline__ void mma16816(float& c0, float& c1, float& c2, float& c3,
                                         uint32_t a0, uint32_t a1, uint32_t a2, uint32_t a3,
                                         uint32_t b0, uint32_t b1) {
    asm volatile("mma.sync.aligned.m16n8k16.row.col.f32.f16.f16.f32 "
                 "{%0,%1,%2,%3}, {%4,%5,%6,%7}, {%8,%9}, {%0,%1,%2,%3};"
                 : "+f"(c0), "+f"(c1), "+f"(c2), "+f"(c3)
                 : "r"(a0), "r"(a1), "r"(a2), "r"(a3), "r"(b0), "r"(b1));
}
__device__ __forceinline__ unsigned int fkey(float f) {
    unsigned int u = __float_as_uint(f);
    return (u & 0x80000000u) ? ~u : (u | 0x80000000u);
}
__device__ __forceinline__ float unfkey(unsigned int k) {
    unsigned int u = (k & 0x80000000u) ? (k & 0x7FFFFFFFu) : ~k;
    return __uint_as_float(u);
}
__device__ __forceinline__ uint32_t swoff(int r, int u) {
    return (uint32_t)(r * 64 + 16 * (u ^ ((r >> 1) & 3)));
}
__device__ __forceinline__ uint32_t pkh(float a, float b) {
    __half h0 = __float2half_rn(a), h1 = __float2half_rn(b);
    return (uint32_t)__half_as_ushort(h0) | ((uint32_t)__half_as_ushort(h1) << 16);
}

// ---------------------------------------------------------------------------
// prep B: codebook -> fp16 HI pre-swizzled tiles. grid (8 nc, 8 stage)
// ---------------------------------------------------------------------------
__global__ __launch_bounds__(256) void prep_b(const float* __restrict__ cb) {
    const int nc = blockIdx.x, stage = blockIdx.y;
    unsigned char* outHi = gB + ((size_t)(nc * 8 + stage)) * 8192;
    #pragma unroll
    for (int v = 0; v < 2; v++) {
        int id = v * 256 + threadIdx.x;
        int r = id >> 2, u = id & 3;
        const float* src = cb + (size_t)(nc * 128 + r) * Dc + stage * 32 + u * 8;
        uint32_t hw_[4];
        #pragma unroll
        for (int p = 0; p < 4; p++)
            hw_[p] = pkh(src[2*p], src[2*p + 1]);
        *reinterpret_cast<uint4*>(outHi + swoff(r, u)) = make_uint4(hw_[0], hw_[1], hw_[2], hw_[3]);
    }
}

// ---------------------------------------------------------------------------
__global__ void cnorm_kernel(const float* __restrict__ cb) {
    if (blockIdx.x == 0 && threadIdx.x == 0) g_nfix = 0;
    int warp = (blockIdx.x * blockDim.x + threadIdx.x) >> 5;
    int lane = threadIdx.x & 31;
    if (warp >= Kc) return;
    const float* row = cb + warp * Dc;
    float s = 0.f;
    #pragma unroll
    for (int d = lane; d < Dc; d += 32) { float v = row[d]; s = fmaf(v, v, s); }
    #pragma unroll
    for (int o = 16; o; o >>= 1) s += __shfl_xor_sync(0xFFFFFFFFu, s, o);
    if (lane == 0) g_cnorm[warp] = s;
}

// ---------------------------------------------------------------------------
// argmin via mma.sync, HI*HI only + top-2 certification.
// A transpose/convert FUSED into the kernel (staging in B-buf1, gated by
// MB_PREP so the producer overlaps B-chunk0 fill with A prep).
// ---------------------------------------------------------------------------
__global__ __launch_bounds__(NTHR, 1) void argmin_mma(const float* __restrict__ x) {
    extern __shared__ __align__(128) unsigned char smem[];
    const uint32_t sb = smem_u32(smem);
    const int tid = threadIdx.x, lane = tid & 31, wid = tid >> 5;
    const int bm = blockIdx.x;

    const uint32_t MB_FULL  = sb + SM_MB;        // full[b]  = +b*8
    const uint32_t MB_EMPTY = sb + SM_MB + 16;   // empty[b] = +b*8
    const uint32_t MB_PREP  = sb + SM_MB + 32;

    float* sm_cn = reinterpret_cast<float*>(smem + SM_CN);
    unsigned long long* sBest = reinterpret_cast<unsigned long long*>(smem + SM_BEST);
    unsigned int* sBest2 = reinterpret_cast<unsigned int*>(smem + SM_BEST2);

    if (tid == 0) {
        #pragma unroll
        for (int b = 0; b < 2; b++) {
            MBAR_INIT(MB_FULL + b * 8, 1);
            MBAR_INIT(MB_EMPTY + b * 8, 16);
        }
        MBAR_INIT(MB_PREP, 16);
    }
    for (int i = tid; i < Kc; i += NTHR) sm_cn[i] = g_cnorm[i];
    if (tid < 128) { sBest[tid] = ~0ull; sBest2[tid] = 0xFFFFFFFFu; }
    __syncthreads();   // mbarriers + tables visible

    if (wid == 16) {
        // ---------------- producer warp ----------------
        if (lane == 0) {
            // chunk 0 immediately (overlaps A prep, which stages in buf1)
            MBAR_EXPECT(MB_FULL + 0, 65536u);
            bulk_copy(sb + SM_B + 0, gB + 0, 65536u, MB_FULL + 0);
            // buf1 only after A prep releases the staging area
            mbar_wait(MB_PREP, 0);
            MBAR_EXPECT(MB_FULL + 8, 65536u);
            bulk_copy(sb + SM_B + 65536, gB + 65536, 65536u, MB_FULL + 8);
            int ep[2] = {0, 0};
            #pragma unroll 1
            for (int nc = 2; nc < NCHUNK; nc++) {
                const int b = nc & 1;
                mbar_wait(MB_EMPTY + b * 8, ep[b]); ep[b] ^= 1;
                MBAR_EXPECT(MB_FULL + b * 8, 65536u);
                bulk_copy(sb + SM_B + b * 65536, gB + (size_t)nc * 65536,
                          65536u, MB_FULL + b * 8);
            }
        }
    } else {
        // ---------------- compute warps (512 threads) ----------------
        // fused A prep: x (b,d,hw) -> token-major fp16 swizzled tiles in SM_A.
        {
            float* stg = reinterpret_cast<float*>(smem + SM_B + 65536); // buf1 as staging
            const int b0  = bm >> 3;
            const int hw0 = (bm & 7) << 7;
            const float* xb = x + (size_t)b0 * Dc * HWc + hw0;
            const int pd = tid >> 4, pq = tid & 15;   // load mapping: row pd, 8 floats @ pq*8
            const int cr = tid >> 2, cu = tid & 3;    // convert mapping: out unit (cr, cu)

            #pragma unroll 1
            for (int s = 0; s < NSTG; s++) {
                const float* srow = xb + (size_t)(s * 32 + pd) * HWc + pq * 8;
                float4 v0 = *reinterpret_cast<const float4*>(srow);
                float4 v1 = *reinterpret_cast<const float4*>(srow + 4);
                float* drow = stg + pd * 132 + pq * 8;
                drow[0] = v0.x; drow[1] = v0.y; drow[2] = v0.z; drow[3] = v0.w;
                drow[4] = v1.x; drow[5] = v1.y; drow[6] = v1.z; drow[7] = v1.w;
                asm volatile("bar.sync 2, 512;" ::: "memory");
                uint32_t hw_[4];
                #pragma unroll
                for (int p = 0; p < 4; p++) {
                    float f0 = stg[(cu * 8 + 2 * p) * 132 + cr];
                    float f1 = stg[(cu * 8 + 2 * p + 1) * 132 + cr];
                    hw_[p] = pkh(f0, f1);
                }
                *reinterpret_cast<uint4*>(smem + SM_A + s * 8192 + swoff(cr, cu)) =
                    make_uint4(hw_[0], hw_[1], hw_[2], hw_[3]);
                asm volatile("bar.sync 2, 512;" ::: "memory");
            }
            if (lane == 0) MBAR_ARRIVE(MB_PREP);   // release buf1 to producer
        }

        const int wm = wid & 3, wn = wid >> 2;
        const int a_r = wm * 32 + (lane & 15);
        const int a_u = lane >> 4;
        const int b_r = wn * 32 + (lane & 7) + ((lane >> 4) << 3);
        const int b_u = (lane >> 3) & 1;

        uint32_t aof[2][2], bof[2][2];
        #pragma unroll
        for (int i = 0; i < 2; i++)
            #pragma unroll
            for (int kk = 0; kk < 2; kk++) {
                aof[i][kk] = swoff(a_r + i * 16, kk * 2 + a_u);
                bof[i][kk] = swoff(b_r + i * 16, kk * 2 + b_u);
            }

        float b1s[4], b2s[4];
        int   b1i[4];
        #pragma unroll
        for (int i = 0; i < 4; i++) { b1s[i] = 3.4e38f; b2s[i] = 3.4e38f; b1i[i] = 0; }

        float acc[2][4][4];
        #pragma unroll
        for (int mi = 0; mi < 2; mi++)
            #pragma unroll
            for (int ni = 0; ni < 4; ni++)
                #pragma unroll
                for (int c = 0; c < 4; c++) acc[mi][ni][c] = 0.f;

        int fpb[2] = {0, 0};

        #pragma unroll 1
        for (int nc = 0; nc < NCHUNK; nc++) {
            const int b = nc & 1;
            mbar_wait(MB_FULL + b * 8, fpb[b]);
            fpb[b] ^= 1;
            const uint32_t bufB = sb + SM_B + b * 65536;

            #pragma unroll 2
            for (int s = 0; s < NSTG; s++) {
                const uint32_t stB = bufB + s * 8192;
                const uint32_t stA = sb + SM_A + s * 8192;

                uint32_t bh0[8], bh1[8];
                #pragma unroll
                for (int np = 0; np < 2; np++) {
                    ldsm4(bh0[np*4+0], bh0[np*4+1], bh0[np*4+2], bh0[np*4+3],
                          stB + bof[np][0]);
                    ldsm4(bh1[np*4+0], bh1[np*4+1], bh1[np*4+2], bh1[np*4+3],
                          stB + bof[np][1]);
                }
                #pragma unroll
                for (int kk = 0; kk < 2; kk++) {
                    const uint32_t* bh = kk ? bh1 : bh0;
                    uint32_t ah[8];
                    #pragma unroll
                    for (int mi = 0; mi < 2; mi++)
                        ldsm4(ah[mi*4+0], ah[mi*4+1], ah[mi*4+2], ah[mi*4+3],
                              stA + aof[mi][kk]);
                    #pragma unroll
                    for (int mi = 0; mi < 2; mi++)
                        #pragma unroll
                        for (int ni = 0; ni < 4; ni++)
                            mma16816(acc[mi][ni][0], acc[mi][ni][1], acc[mi][ni][2], acc[mi][ni][3],
                                     ah[mi*4+0], ah[mi*4+1], ah[mi*4+2], ah[mi*4+3],
                                     bh[(ni>>1)*4 + (ni&1)*2], bh[(ni>>1)*4 + (ni&1)*2 + 1]);
                }
            }
            if (lane == 0) MBAR_ARRIVE(MB_EMPTY + b * 8);

            #pragma unroll
            for (int mi = 0; mi < 2; mi++)
                #pragma unroll
                for (int ni = 0; ni < 4; ni++)
                    #pragma unroll
                    for (int c = 0; c < 4; c++) {
                        int code = nc * 128 + wn * 32 + ni * 8 + (lane & 3) * 2 + (c & 1);
                        float score = fmaf(-2.f, acc[mi][ni][c], sm_cn[code]);
                        int slot = mi * 2 + (c >> 1);
                        if (score < b1s[slot]) {
                            b2s[slot] = b1s[slot];
                            b1s[slot] = score; b1i[slot] = code;
                        } else if (score < b2s[slot]) {
                            b2s[slot] = score;
                        }
                        acc[mi][ni][c] = 0.f;
                    }
        }

        unsigned long long pk[4];
        #pragma unroll
        for (int slot = 0; slot < 4; slot++) {
            int row = wm * 32 + (slot >> 1) * 16 + (lane >> 2) + 8 * (slot & 1);
            pk[slot] = ((unsigned long long)fkey(b1s[slot]) << 32) | (unsigned int)b1i[slot];
            atomicMin(&sBest[row], pk[slot]);
        }
        asm volatile("bar.sync 1, 512;" ::: "memory");
        #pragma unroll
        for (int slot = 0; slot < 4; slot++) {
            int row = wm * 32 + (slot >> 1) * 16 + (lane >> 2) + 8 * (slot & 1);
            float cand = (pk[slot] == sBest[row]) ? b2s[slot] : b1s[slot];
            atomicMin(&sBest2[row], fkey(cand));
        }
    }

    __syncthreads();
    if (tid < 128) {
        unsigned long long win = sBest[tid];
        const int token = bm * M_TILE + tid;
        g_idx[token] = (int)(unsigned int)(win & 0xFFFFFFFFull);
        float s1 = unfkey((unsigned int)(win >> 32));
        float s2 = unfkey(sBest2[tid]);
        if (s2 - s1 < THRESH) {
            int p = atomicAdd(&g_nfix, 1);
            g_fixlist[p] = token;
            g_fixbest[p] = ~0ull;
        }
    }
}

// ---------------------------------------------------------------------------
// fixup v3: split-work exact fp32 GEMM argmin.
// ---------------------------------------------------------------------------
__global__ __launch_bounds__(256) void fixup_gemm(const float* __restrict__ x,
                                                  const float* __restrict__ cb)
{
    extern __shared__ __align__(16) unsigned char fsm[];
    float* xsF = reinterpret_cast<float*>(fsm + FX_XS);
    float* cbT = reinterpret_cast<float*>(fsm + FX_CBT);
    unsigned long long* sbt = reinterpret_cast<unsigned long long*>(fsm + FX_SB);

    const int tid = threadIdx.x;
    const int nfix = g_nfix;
    if (nfix == 0) return;
    const int ngrp = (nfix + FTOK - 1) / FTOK;
    const int nitems = ngrp * 4;
    const int tg = tid >> 6;
    const int tc = tid & 63;

    #pragma unroll 1
    for (int item = blockIdx.x; item < nitems; item += gridDim.x) {
        const int g = item >> 2, cc = item & 3;
        const int base = g * FTOK;
        const int nb = min(FTOK, nfix - base);

        for (int i = tid; i < FTOK * 64; i += 256) {
            int tt = i >> 6, q = i & 63;
            if (tt < nb) {
                int n = g_fixlist[base + tt];
                int b = n >> 10, hw = n & (HWc - 1);
                const float* xp = x + (size_t)b * Dc * HWc + hw;
                float4 v;
                v.x = xp[(size_t)(q * 4 + 0) * HWc];
                v.y = xp[(size_t)(q * 4 + 1) * HWc];
                v.z = xp[(size_t)(q * 4 + 2) * HWc];
                v.w = xp[(size_t)(q * 4 + 3) * HWc];
                *reinterpret_cast<float4*>(&xsF[tt * 256 + q * 4]) = v;
            }
        }
        if (tid < FTOK) sbt[tid] = ~0ull;

        float acc[4][4];
        #pragma unroll
        for (int i = 0; i < 4; i++)
            #pragma unroll
            for (int j = 0; j < 4; j++) acc[i][j] = 0.f;

        #pragma unroll 1
        for (int ks = 0; ks < 8; ks++) {
            {
                const float* src = cb + (size_t)(cc * 256 + tid) * Dc + ks * 32;
                #pragma unroll
                for (int q = 0; q < 8; q++) {
                    float4 v = *reinterpret_cast<const float4*>(src + q * 4);
                    cbT[(q * 4 + 0) * 256 + tid] = v.x;
                    cbT[(q * 4 + 1) * 256 + tid] = v.y;
                    cbT[(q * 4 + 2) * 256 + tid] = v.z;
                    cbT[(q * 4 + 3) * 256 + tid] = v.w;
                }
            }
            __syncthreads();
            #pragma unroll
            for (int k = 0; k < 32; k++) {
                float4 bv = *reinterpret_cast<const float4*>(&cbT[k * 256 + tc * 4]);
                #pragma unroll
                for (int i = 0; i < 4; i++) {
                    float a = xsF[(tg * 4 + i) * 256 + ks * 32 + k];
                    acc[i][0] = fmaf(a, bv.x, acc[i][0]);
                    acc[i][1] = fmaf(a, bv.y, acc[i][1]);
                    acc[i][2] = fmaf(a, bv.z, acc[i][2]);
                    acc[i][3] = fmaf(a, bv.w, acc[i][3]);
                }
            }
            __syncthreads();
        }

        #pragma unroll
        for (int i = 0; i < 4; i++) {
            int tok = tg * 4 + i;
            unsigned long long mymin = ~0ull;
            #pragma unroll
            for (int j = 0; j < 4; j++) {
                int code = cc * 256 + tc * 4 + j;
                float score = fmaf(-2.f, acc[i][j], g_cnorm[code]);
                unsigned long long pack =
                    ((unsigned long long)fkey(score) << 32) | (unsigned int)code;
                if (pack < mymin) mymin = pack;
            }
            if (tok < nb) atomicMin(&sbt[tok], mymin);
        }
        __syncthreads();
        if (tid < nb) atomicMin(&g_fixbest[base + tid], sbt[tid]);
        __syncthreads();
    }
}

// ---------------------------------------------------------------------------
__global__ __launch_bounds__(256) void fix_finalize() {
    const int nfix = g_nfix;
    for (int i = blockIdx.x * blockDim.x + threadIdx.x; i < nfix;
         i += gridDim.x * blockDim.x)
        g_idx[g_fixlist[i]] = (int)(unsigned int)(g_fixbest[i] & 0xFFFFFFFFull);
}

// ---------------------------------------------------------------------------
__global__ void output_kernel(const float* __restrict__ cb,
                              float* __restrict__ zhat,
                              float* __restrict__ zq)
{
    int t = blockIdx.x * blockDim.x + threadIdx.x;
    if (t >= NELEM / 4) return;
    int n  = t >> 6;
    int d4 = t & 63;
    int k  = g_idx[n];
    float4 c = *reinterpret_cast<const float4*>(cb + (size_t)k * Dc + d4 * 4);
    *reinterpret_cast<float4*>(zq   + (size_t)t * 4) = c;
    *reinterpret_cast<float4*>(zhat + (size_t)t * 4) = c;
}

// ---------------------------------------------------------------------------
extern "C" void kernel_launch(void* const* d_in, const int* in_sizes, int n_in,
                              void* d_out, int out_size)
{
    const float* x  = (const float*)d_in[0];
    const float* cb = (const float*)d_in[1];
    float* zhat = (float*)d_out;
    float* zq   = (float*)d_out + NELEM;

    static int attr_set = 0;
    if (!attr_set) {
        cudaFuncSetAttribute(argmin_mma, cudaFuncAttributeMaxDynamicSharedMemorySize, SM_TOTAL);
        cudaFuncSetAttribute(fixup_gemm, cudaFuncAttributeMaxDynamicSharedMemorySize, FX_TOTAL);
        attr_set = 1;
    }

    prep_b<<<dim3(8, NSTG), 256>>>(cb);
    cnorm_kernel<<<Kc / 8, 256>>>(cb);
    argmin_mma<<<NBLK, NTHR, SM_TOTAL>>>(x);
    fixup_gemm<<<444, 256, FX_TOTAL>>>(x, cb);
    fix_finalize<<<64, 256>>>();
    output_kernel<<<(NELEM / 4 + 255) / 256, 256>>>(cb, zhat, zq);
}

// round 15
// speedup vs baseline: 1.0953x; 1.0953x over previous
#include <cuda_runtime.h>
#include <cuda_fp16.h>
#include <cstdint>

// Problem constants
#define Dc     256
#define Kc     1024
#define HWc    1024
#define NTOK   65536
#define NELEM  16777216

#define NBLK   512          // token blocks of 128
#define M_TILE 128
#define NCHUNK 8
#define NSTG   8
#define NTHR   544          // 16 compute warps + 1 producer warp
#define THRESH 0.25f
#define FTOK   16           // tokens per fixup work-item group

// PRE-SWIZZLED fp16-hi codebook image + fp32 TRANSPOSED codebook:
__device__ __align__(128) unsigned char gB[8 * 8 * 8192];           // 512 KB
__device__ __align__(128) float gCbT[Dc * Kc];                      // 1 MB, [d][code]
__device__ float g_cnorm[Kc];
__device__ int   g_idx[NTOK];
__device__ int   g_nfix;
__device__ int   g_fixlist[NTOK];
__device__ unsigned long long g_fixbest[NTOK];

// dynamic smem layout (argmin kernel)
#define SM_A     0          // 64KB: 8 stage tiles (fp16, swizzled)
#define SM_B     65536      // 2 chunk buffers x 64KB (buf1 doubles as f32 prep staging)
#define SM_CN    196608     // 4KB
#define SM_BEST  200704     // 1KB
#define SM_BEST2 201728     // 512B
#define SM_MB    202240     // full[2] @ +0, empty[2] @ +16, prep @ +32
#define SM_TOTAL 202368

// dynamic smem layout (fixup kernel)
#define FX_XS    0          // [16][256] f32 = 16KB
#define FX_CBT   16384      // [32][256] f32 = 32KB  (d-major)
#define FX_SB    49152      // [16] u64
#define FX_TOTAL 49280

__device__ __forceinline__ uint32_t smem_u32(const void* p) {
    uint32_t a;
    asm("{ .reg .u64 t; cvta.to.shared.u64 t, %1; cvt.u32.u64 %0, t; }" : "=r"(a) : "l"(p));
    return a;
}
__device__ __forceinline__ void bulk_copy(uint32_t dst, const void* src,
                                          uint32_t bytes, uint32_t mbar) {
    asm volatile(
        "cp.async.bulk.shared::cluster.global.mbarrier::complete_tx::bytes "
        "[%0], [%1], %2, [%3];"
        :: "r"(dst), "l"(src), "r"(bytes), "r"(mbar) : "memory");
}
#define MBAR_INIT(a, c)   asm volatile("mbarrier.init.shared.b64 [%0], %1;" :: "r"(a), "r"(c) : "memory")
#define MBAR_EXPECT(a, b) asm volatile("mbarrier.arrive.expect_tx.shared.b64 _, [%0], %1;" :: "r"(a), "r"(b) : "memory")
#define MBAR_ARRIVE(a)    asm volatile("mbarrier.arrive.shared.b64 _, [%0];" :: "r"(a) : "memory")

__device__ __forceinline__ void mbar_wait(uint32_t mbar, uint32_t parity) {
    asm volatile(
        "{\n\t.reg .pred P1;\n\t"
        "WAIT_LOOP_%=:\n\t"
        "mbarrier.try_wait.parity.acquire.cta.shared::cta.b64 P1, [%0], %1, 0x989680;\n\t"
        "@P1 bra.uni WAIT_DONE_%=;\n\t"
        "bra.uni WAIT_LOOP_%=;\n\t"
        "WAIT_DONE_%=:\n\t}"
        :: "r"(mbar), "r"(parity) : "memory");
}

__device__ __forceinline__ void ldsm4(uint32_t& r0, uint32_t& r1, uint32_t& r2, uint32_t& r3,
                                      uint32_t addr) {
    asm volatile("ldmatrix.sync.aligned.m8n8.x4.shared.b16 {%0,%1,%2,%3}, [%4];"
                 : "=r"(r0), "=r"(r1), "=r"(r2), "=r"(r3) : "r"(addr));
}
__device__ __forceinline__ void mma16816(float& c0, float& c1, float& c2, float& c3,
                                         uint32_t a0, uint32_t a1, uint32_t a2, uint32_t a3,
                                         uint32_t b0, uint32_t b1) {
    asm volatile("mma.sync.aligned.m16n8k16.row.col.f32.f16.f16.f32 "
                 "{%0,%1,%2,%3}, {%4,%5,%6,%7}, {%8,%9}, {%0,%1,%2,%3};"
                 : "+f"(c0), "+f"(c1), "+f"(c2), "+f"(c3)
                 : "r"(a0), "r"(a1), "r"(a2), "r"(a3), "r"(b0), "r"(b1));
}
__device__ __forceinline__ unsigned int fkey(float f) {
    unsigned int u = __float_as_uint(f);
    return (u & 0x80000000u) ? ~u : (u | 0x80000000u);
}
__device__ __forceinline__ float unfkey(unsigned int k) {
    unsigned int u = (k & 0x80000000u) ? (k & 0x7FFFFFFFu) : ~k;
    return __uint_as_float(u);
}
__device__ __forceinline__ uint32_t swoff(int r, int u) {
    return (uint32_t)(r * 64 + 16 * (u ^ ((r >> 1) & 3)));
}
__device__ __forceinline__ uint32_t pkh(float a, float b) {
    __half h0 = __float2half_rn(a), h1 = __float2half_rn(b);
    return (uint32_t)__half_as_ushort(h0) | ((uint32_t)__half_as_ushort(h1) << 16);
}

// ---------------------------------------------------------------------------
// prep B: codebook -> fp16 HI pre-swizzled tiles. grid (8 nc, 8 stage)
// ---------------------------------------------------------------------------
__global__ __launch_bounds__(256) void prep_b(const float* __restrict__ cb) {
    const int nc = blockIdx.x, stage = blockIdx.y;
    unsigned char* outHi = gB + ((size_t)(nc * 8 + stage)) * 8192;
    #pragma unroll
    for (int v = 0; v < 2; v++) {
        int id = v * 256 + threadIdx.x;
        int r = id >> 2, u = id & 3;
        const float* src = cb + (size_t)(nc * 128 + r) * Dc + stage * 32 + u * 8;
        uint32_t hw_[4];
        #pragma unroll
        for (int p = 0; p < 4; p++)
            hw_[p] = pkh(src[2*p], src[2*p + 1]);
        *reinterpret_cast<uint4*>(outHi + swoff(r, u)) = make_uint4(hw_[0], hw_[1], hw_[2], hw_[3]);
    }
}

// ---------------------------------------------------------------------------
// prep cbT: transpose cb [1024 codes][256 d] -> gCbT [256 d][1024 codes].
// ---------------------------------------------------------------------------
__global__ __launch_bounds__(256) void prep_cbt(const float* __restrict__ cb) {
    __shared__ float tile[32][33];
    const int c0 = blockIdx.x * 32, d0 = blockIdx.y * 32;
    const int tx = threadIdx.x & 31, ty0 = threadIdx.x >> 5;   // 32 x 8
    #pragma unroll
    for (int i = 0; i < 4; i++) {
        int ty = ty0 + i * 8;
        tile[ty][tx] = cb[(size_t)(c0 + ty) * Dc + d0 + tx];   // coalesced over d
    }
    __syncthreads();
    #pragma unroll
    for (int i = 0; i < 4; i++) {
        int ty = ty0 + i * 8;
        gCbT[(size_t)(d0 + ty) * Kc + c0 + tx] = tile[tx][ty]; // coalesced over codes
    }
}

// ---------------------------------------------------------------------------
__global__ void cnorm_kernel(const float* __restrict__ cb) {
    if (blockIdx.x == 0 && threadIdx.x == 0) g_nfix = 0;
    int warp = (blockIdx.x * blockDim.x + threadIdx.x) >> 5;
    int lane = threadIdx.x & 31;
    if (warp >= Kc) return;
    const float* row = cb + warp * Dc;
    float s = 0.f;
    #pragma unroll
    for (int d = lane; d < Dc; d += 32) { float v = row[d]; s = fmaf(v, v, s); }
    #pragma unroll
    for (int o = 16; o; o >>= 1) s += __shfl_xor_sync(0xFFFFFFFFu, s, o);
    if (lane == 0) g_cnorm[warp] = s;
}

// ---------------------------------------------------------------------------
// argmin via mma.sync, HI*HI only + top-2 certification (unchanged from R12).
// ---------------------------------------------------------------------------
__global__ __launch_bounds__(NTHR, 1) void argmin_mma(const float* __restrict__ x) {
    extern __shared__ __align__(128) unsigned char smem[];
    const uint32_t sb = smem_u32(smem);
    const int tid = threadIdx.x, lane = tid & 31, wid = tid >> 5;
    const int bm = blockIdx.x;

    const uint32_t MB_FULL  = sb + SM_MB;
    const uint32_t MB_EMPTY = sb + SM_MB + 16;
    const uint32_t MB_PREP  = sb + SM_MB + 32;

    float* sm_cn = reinterpret_cast<float*>(smem + SM_CN);
    unsigned long long* sBest = reinterpret_cast<unsigned long long*>(smem + SM_BEST);
    unsigned int* sBest2 = reinterpret_cast<unsigned int*>(smem + SM_BEST2);

    if (tid == 0) {
        #pragma unroll
        for (int b = 0; b < 2; b++) {
            MBAR_INIT(MB_FULL + b * 8, 1);
            MBAR_INIT(MB_EMPTY + b * 8, 16);
        }
        MBAR_INIT(MB_PREP, 16);
    }
    for (int i = tid; i < Kc; i += NTHR) sm_cn[i] = g_cnorm[i];
    if (tid < 128) { sBest[tid] = ~0ull; sBest2[tid] = 0xFFFFFFFFu; }
    __syncthreads();

    if (wid == 16) {
        // producer warp
        if (lane == 0) {
            MBAR_EXPECT(MB_FULL + 0, 65536u);
            bulk_copy(sb + SM_B + 0, gB + 0, 65536u, MB_FULL + 0);
            mbar_wait(MB_PREP, 0);
            MBAR_EXPECT(MB_FULL + 8, 65536u);
            bulk_copy(sb + SM_B + 65536, gB + 65536, 65536u, MB_FULL + 8);
            int ep[2] = {0, 0};
            #pragma unroll 1
            for (int nc = 2; nc < NCHUNK; nc++) {
                const int b = nc & 1;
                mbar_wait(MB_EMPTY + b * 8, ep[b]); ep[b] ^= 1;
                MBAR_EXPECT(MB_FULL + b * 8, 65536u);
                bulk_copy(sb + SM_B + b * 65536, gB + (size_t)nc * 65536,
                          65536u, MB_FULL + b * 8);
            }
        }
    } else {
        // fused A prep
        {
            float* stg = reinterpret_cast<float*>(smem + SM_B + 65536);
            const int b0  = bm >> 3;
            const int hw0 = (bm & 7) << 7;
            const float* xb = x + (size_t)b0 * Dc * HWc + hw0;
            const int pd = tid >> 4, pq = tid & 15;
            const int cr = tid >> 2, cu = tid & 3;

            #pragma unroll 1
            for (int s = 0; s < NSTG; s++) {
                const float* srow = xb + (size_t)(s * 32 + pd) * HWc + pq * 8;
                float4 v0 = *reinterpret_cast<const float4*>(srow);
                float4 v1 = *reinterpret_cast<const float4*>(srow + 4);
                float* drow = stg + pd * 132 + pq * 8;
                drow[0] = v0.x; drow[1] = v0.y; drow[2] = v0.z; drow[3] = v0.w;
                drow[4] = v1.x; drow[5] = v1.y; drow[6] = v1.z; drow[7] = v1.w;
                asm volatile("bar.sync 2, 512;" ::: "memory");
                uint32_t hw_[4];
                #pragma unroll
                for (int p = 0; p < 4; p++) {
                    float f0 = stg[(cu * 8 + 2 * p) * 132 + cr];
                    float f1 = stg[(cu * 8 + 2 * p + 1) * 132 + cr];
                    hw_[p] = pkh(f0, f1);
                }
                *reinterpret_cast<uint4*>(smem + SM_A + s * 8192 + swoff(cr, cu)) =
                    make_uint4(hw_[0], hw_[1], hw_[2], hw_[3]);
                asm volatile("bar.sync 2, 512;" ::: "memory");
            }
            if (lane == 0) MBAR_ARRIVE(MB_PREP);
        }

        const int wm = wid & 3, wn = wid >> 2;
        const int a_r = wm * 32 + (lane & 15);
        const int a_u = lane >> 4;
        const int b_r = wn * 32 + (lane & 7) + ((lane >> 4) << 3);
        const int b_u = (lane >> 3) & 1;

        uint32_t aof[2][2], bof[2][2];
        #pragma unroll
        for (int i = 0; i < 2; i++)
            #pragma unroll
            for (int kk = 0; kk < 2; kk++) {
                aof[i][kk] = swoff(a_r + i * 16, kk * 2 + a_u);
                bof[i][kk] = swoff(b_r + i * 16, kk * 2 + b_u);
            }

        float b1s[4], b2s[4];
        int   b1i[4];
        #pragma unroll
        for (int i = 0; i < 4; i++) { b1s[i] = 3.4e38f; b2s[i] = 3.4e38f; b1i[i] = 0; }

        float acc[2][4][4];
        #pragma unroll
        for (int mi = 0; mi < 2; mi++)
            #pragma unroll
            for (int ni = 0; ni < 4; ni++)
                #pragma unroll
                for (int c = 0; c < 4; c++) acc[mi][ni][c] = 0.f;

        int fpb[2] = {0, 0};

        #pragma unroll 1
        for (int nc = 0; nc < NCHUNK; nc++) {
            const int b = nc & 1;
            mbar_wait(MB_FULL + b * 8, fpb[b]);
            fpb[b] ^= 1;
            const uint32_t bufB = sb + SM_B + b * 65536;

            #pragma unroll 2
            for (int s = 0; s < NSTG; s++) {
                const uint32_t stB = bufB + s * 8192;
                const uint32_t stA = sb + SM_A + s * 8192;

                uint32_t bh0[8], bh1[8];
                #pragma unroll
                for (int np = 0; np < 2; np++) {
                    ldsm4(bh0[np*4+0], bh0[np*4+1], bh0[np*4+2], bh0[np*4+3],
                          stB + bof[np][0]);
                    ldsm4(bh1[np*4+0], bh1[np*4+1], bh1[np*4+2], bh1[np*4+3],
                          stB + bof[np][1]);
                }
                #pragma unroll
                for (int kk = 0; kk < 2; kk++) {
                    const uint32_t* bh = kk ? bh1 : bh0;
                    uint32_t ah[8];
                    #pragma unroll
                    for (int mi = 0; mi < 2; mi++)
                        ldsm4(ah[mi*4+0], ah[mi*4+1], ah[mi*4+2], ah[mi*4+3],
                              stA + aof[mi][kk]);
                    #pragma unroll
                    for (int mi = 0; mi < 2; mi++)
                        #pragma unroll
                        for (int ni = 0; ni < 4; ni++)
                            mma16816(acc[mi][ni][0], acc[mi][ni][1], acc[mi][ni][2], acc[mi][ni][3],
                                     ah[mi*4+0], ah[mi*4+1], ah[mi*4+2], ah[mi*4+3],
                                     bh[(ni>>1)*4 + (ni&1)*2], bh[(ni>>1)*4 + (ni&1)*2 + 1]);
                }
            }
            if (lane == 0) MBAR_ARRIVE(MB_EMPTY + b * 8);

            #pragma unroll
            for (int mi = 0; mi < 2; mi++)
                #pragma unroll
                for (int ni = 0; ni < 4; ni++)
                    #pragma unroll
                    for (int c = 0; c < 4; c++) {
                        int code = nc * 128 + wn * 32 + ni * 8 + (lane & 3) * 2 + (c & 1);
                        float score = fmaf(-2.f, acc[mi][ni][c], sm_cn[code]);
                        int slot = mi * 2 + (c >> 1);
                        if (score < b1s[slot]) {
                            b2s[slot] = b1s[slot];
                            b1s[slot] = score; b1i[slot] = code;
                        } else if (score < b2s[slot]) {
                            b2s[slot] = score;
                        }
                        acc[mi][ni][c] = 0.f;
                    }
        }

        unsigned long long pk[4];
        #pragma unroll
        for (int slot = 0; slot < 4; slot++) {
            int row = wm * 32 + (slot >> 1) * 16 + (lane >> 2) + 8 * (slot & 1);
            pk[slot] = ((unsigned long long)fkey(b1s[slot]) << 32) | (unsigned int)b1i[slot];
            atomicMin(&sBest[row], pk[slot]);
        }
        asm volatile("bar.sync 1, 512;" ::: "memory");
        #pragma unroll
        for (int slot = 0; slot < 4; slot++) {
            int row = wm * 32 + (slot >> 1) * 16 + (lane >> 2) + 8 * (slot & 1);
            float cand = (pk[slot] == sBest[row]) ? b2s[slot] : b1s[slot];
            atomicMin(&sBest2[row], fkey(cand));
        }
    }

    __syncthreads();
    if (tid < 128) {
        unsigned long long win = sBest[tid];
        const int token = bm * M_TILE + tid;
        g_idx[token] = (int)(unsigned int)(win & 0xFFFFFFFFull);
        float s1 = unfkey((unsigned int)(win >> 32));
        float s2 = unfkey(sBest2[tid]);
        if (s2 - s1 < THRESH) {
            int p = atomicAdd(&g_nfix, 1);
            g_fixlist[p] = token;
            g_fixbest[p] = ~0ull;
        }
    }
}

// ---------------------------------------------------------------------------
// fixup v4 (FIXED): full 32x256 tile load (2048 float4 units, v<8).
// ---------------------------------------------------------------------------
__global__ __launch_bounds__(256) void fixup_gemm(const float* __restrict__ x)
{
    extern __shared__ __align__(16) unsigned char fsm[];
    float* xsF = reinterpret_cast<float*>(fsm + FX_XS);    // [16][256]
    float* cbT = reinterpret_cast<float*>(fsm + FX_CBT);   // [32 d][256 codes]
    unsigned long long* sbt = reinterpret_cast<unsigned long long*>(fsm + FX_SB);

    const int tid = threadIdx.x;
    const int nfix = g_nfix;
    if (nfix == 0) return;
    const int ngrp = (nfix + FTOK - 1) / FTOK;
    const int nitems = ngrp * 4;
    const int tg = tid >> 6;     // token subgroup 0..3 (4 tokens each)
    const int tc = tid & 63;     // code subgroup (4 codes each)

    #pragma unroll 1
    for (int item = blockIdx.x; item < nitems; item += gridDim.x) {
        const int g = item >> 2, cc = item & 3;
        const int base = g * FTOK;
        const int nb = min(FTOK, nfix - base);

        for (int i = tid; i < FTOK * 64; i += 256) {
            int tt = i >> 6, q = i & 63;
            if (tt < nb) {
                int n = g_fixlist[base + tt];
                int b = n >> 10, hw = n & (HWc - 1);
                const float* xp = x + (size_t)b * Dc * HWc + hw;
                float4 v;
                v.x = xp[(size_t)(q * 4 + 0) * HWc];
                v.y = xp[(size_t)(q * 4 + 1) * HWc];
                v.z = xp[(size_t)(q * 4 + 2) * HWc];
                v.w = xp[(size_t)(q * 4 + 3) * HWc];
                *reinterpret_cast<float4*>(&xsF[tt * 256 + q * 4]) = v;
            }
        }
        if (tid < FTOK) sbt[tid] = ~0ull;

        float acc[4][4];
        #pragma unroll
        for (int i = 0; i < 4; i++)
            #pragma unroll
            for (int j = 0; j < 4; j++) acc[i][j] = 0.f;

        #pragma unroll 1
        for (int ks = 0; ks < 8; ks++) {
            // load FULL 32-d x 256-code tile from gCbT: 2048 float4 units
            {
                const float* src = gCbT + (size_t)(ks * 32) * Kc + cc * 256;
                #pragma unroll
                for (int v = 0; v < 8; v++) {
                    int i = v * 256 + tid;          // 2048 float4 units
                    int r = i >> 6, q = i & 63;     // d-row 0..31, code-float4 0..63
                    *reinterpret_cast<float4*>(&cbT[r * 256 + q * 4]) =
                        *reinterpret_cast<const float4*>(src + (size_t)r * Kc + q * 4);
                }
            }
            __syncthreads();
            #pragma unroll
            for (int k = 0; k < 32; k++) {
                float4 bv = *reinterpret_cast<const float4*>(&cbT[k * 256 + tc * 4]);
                #pragma unroll
                for (int i = 0; i < 4; i++) {
                    float a = xsF[(tg * 4 + i) * 256 + ks * 32 + k];
                    acc[i][0] = fmaf(a, bv.x, acc[i][0]);
                    acc[i][1] = fmaf(a, bv.y, acc[i][1]);
                    acc[i][2] = fmaf(a, bv.z, acc[i][2]);
                    acc[i][3] = fmaf(a, bv.w, acc[i][3]);
                }
            }
            __syncthreads();
        }

        #pragma unroll
        for (int i = 0; i < 4; i++) {
            int tok = tg * 4 + i;
            unsigned long long mymin = ~0ull;
            #pragma unroll
            for (int j = 0; j < 4; j++) {
                int code = cc * 256 + tc * 4 + j;
                float score = fmaf(-2.f, acc[i][j], g_cnorm[code]);
                unsigned long long pack =
                    ((unsigned long long)fkey(score) << 32) | (unsigned int)code;
                if (pack < mymin) mymin = pack;
            }
            if (tok < nb) atomicMin(&sbt[tok], mymin);
        }
        __syncthreads();
        if (tid < nb) atomicMin(&g_fixbest[base + tid], sbt[tid]);
        __syncthreads();
    }
}

// ---------------------------------------------------------------------------
__global__ __launch_bounds__(256) void fix_finalize() {
    const int nfix = g_nfix;
    for (int i = blockIdx.x * blockDim.x + threadIdx.x; i < nfix;
         i += gridDim.x * blockDim.x)
        g_idx[g_fixlist[i]] = (int)(unsigned int)(g_fixbest[i] & 0xFFFFFFFFull);
}

// ---------------------------------------------------------------------------
__global__ void output_kernel(const float* __restrict__ cb,
                              float* __restrict__ zhat,
                              float* __restrict__ zq)
{
    int t = blockIdx.x * blockDim.x + threadIdx.x;
    if (t >= NELEM / 4) return;
    int n  = t >> 6;
    int d4 = t & 63;
    int k  = g_idx[n];
    float4 c = *reinterpret_cast<const float4*>(cb + (size_t)k * Dc + d4 * 4);
    *reinterpret_cast<float4*>(zq   + (size_t)t * 4) = c;
    *reinterpret_cast<float4*>(zhat + (size_t)t * 4) = c;
}

// ---------------------------------------------------------------------------
extern "C" void kernel_launch(void* const* d_in, const int* in_sizes, int n_in,
                              void* d_out, int out_size)
{
    const float* x  = (const float*)d_in[0];
    const float* cb = (const float*)d_in[1];
    float* zhat = (float*)d_out;
    float* zq   = (float*)d_out + NELEM;

    static int attr_set = 0;
    if (!attr_set) {
        cudaFuncSetAttribute(argmin_mma, cudaFuncAttributeMaxDynamicSharedMemorySize, SM_TOTAL);
        cudaFuncSetAttribute(fixup_gemm, cudaFuncAttributeMaxDynamicSharedMemorySize, FX_TOTAL);
        attr_set = 1;
    }

    prep_b<<<dim3(8, NSTG), 256>>>(cb);
    prep_cbt<<<dim3(32, 8), 256>>>(cb);
    cnorm_kernel<<<Kc / 8, 256>>>(cb);
    argmin_mma<<<NBLK, NTHR, SM_TOTAL>>>(x);
    fixup_gemm<<<444, 256, FX_TOTAL>>>(x);
    fix_finalize<<<64, 256>>>();
    output_kernel<<<(NELEM / 4 + 255) / 256, 256>>>(cb, zhat, zq);
}